// round 3
// baseline (speedup 1.0000x reference)
#include <cuda_runtime.h>
#include <math.h>
#include <stdint.h>

// Problem constants (fixed shapes for this problem)
#define NN   8192      // nodes (= output classes)
#define FIN  512       // input features
#define HD   64        // hidden dim
#define MAXE (NN * 64) // edges

// ---------------- device scratch (static allocation; no cudaMalloc) ----------------
__device__ int   g_is64;             // edge_index dtype flag (1 = int64, 0 = int32)
__device__ int   g_hist[NN];         // in-degree histogram (dst counts)
__device__ int   g_row_ptr[NN + 1];  // CSR row pointers (by dst)
__device__ int   g_cursor[NN];       // scatter cursors
__device__ int   g_col[MAXE];        // CSR column (src) indices
__device__ float g_dinv[NN];         // deg^{-1/2} (deg includes self loop)
__device__ float g_xw[NN * HD];      // x @ W1
__device__ float g_h[NN * HD];       // layer-1 output (post relu)
__device__ float g_m[NN * HD];       // Â h  (layer-2 aggregated hidden)

// ---------------- helpers ----------------
__device__ __forceinline__ int edge_val(const void* ei, long long i) {
    // edge_index may be int64 (reference asks for it) or int32 (default JAX x64-off)
    if (g_is64) return (int)((const long long*)ei)[i];
    return ((const int*)ei)[i];
}

// ---------------- kernel 0: zero counters + detect int width ----------------
__global__ void k_init_detect(const int* eiw) {
    int t = blockIdx.x * blockDim.x + threadIdx.x;
    if (t < NN) { g_hist[t] = 0; g_cursor[t] = 0; }
    if (blockIdx.x == 0) {
        // Inspect the first 1024 "odd" 32-bit words. If the data is int64 with
        // small nonnegative values, all of them are zero. If int32, they are
        // random node ids (zero with prob 1/8192).
        __shared__ int cnt;
        if (threadIdx.x == 0) cnt = 0;
        __syncthreads();
        int c = 0;
        for (int i = threadIdx.x; i < 1024; i += blockDim.x)
            if (eiw[2 * i + 1] == 0) c++;
        atomicAdd(&cnt, c);
        __syncthreads();
        if (threadIdx.x == 0) g_is64 = (cnt > 900) ? 1 : 0;
    }
}

// ---------------- kernel 1: histogram of dst ----------------
__global__ void k_hist(const void* ei, int E) {
    int e = blockIdx.x * blockDim.x + threadIdx.x;
    if (e < E) {
        int d = edge_val(ei, (long long)E + e);
        atomicAdd(&g_hist[d], 1);
    }
}

// ---------------- kernel 2: exclusive scan (1 block, 1024 threads, 8 elems each)
//                  also computes dinv = rsqrt(deg + 1 selfloop) ----------------
__global__ void k_scan() {
    int t = threadIdx.x;
    int vals[8];
    int tsum = 0;
#pragma unroll
    for (int j = 0; j < 8; j++) { vals[j] = g_hist[t * 8 + j]; tsum += vals[j]; }

    int lane = t & 31, wid = t >> 5;
    int incl = tsum;
#pragma unroll
    for (int off = 1; off < 32; off <<= 1) {
        int v = __shfl_up_sync(0xffffffffu, incl, off);
        if (lane >= off) incl += v;
    }
    __shared__ int wsum[32];
    if (lane == 31) wsum[wid] = incl;
    __syncthreads();
    if (wid == 0) {
        int v = wsum[lane];
        int iv = v;
#pragma unroll
        for (int off = 1; off < 32; off <<= 1) {
            int u = __shfl_up_sync(0xffffffffu, iv, off);
            if (lane >= off) iv += u;
        }
        wsum[lane] = iv - v;  // exclusive warp prefix
    }
    __syncthreads();
    int run = wsum[wid] + (incl - tsum);  // exclusive prefix for this thread
#pragma unroll
    for (int j = 0; j < 8; j++) {
        int idx = t * 8 + j;
        g_row_ptr[idx] = run;
        g_dinv[idx] = rsqrtf((float)vals[j] + 1.0f);  // +1 self loop
        run += vals[j];
    }
    if (t == 1023) g_row_ptr[NN] = run;
}

// ---------------- kernel 3: scatter src into CSR ----------------
__global__ void k_scatter(const void* ei, int E) {
    int e = blockIdx.x * blockDim.x + threadIdx.x;
    if (e < E) {
        int s = edge_val(ei, e);
        int d = edge_val(ei, (long long)E + e);
        int pos = g_row_ptr[d] + atomicAdd(&g_cursor[d], 1);
        g_col[pos] = s;
    }
}

// ---------------- kernel 4: XW = x(8192x512) @ W1(512x64) ----------------
// 64 rows x 64 cols per block, 256 threads, each thread 4x4 outputs.
__global__ void k_xw(const float* __restrict__ x, const float* __restrict__ W1) {
    __shared__ float xs[64][33];  // [row][k] chunk of 32
    __shared__ float ws[32][64];  // [k][col]
    int row0 = blockIdx.x * 64;
    int tx = threadIdx.x & 15, ty = threadIdx.x >> 4;
    float acc[4][4] = {};
    for (int k0 = 0; k0 < FIN; k0 += 32) {
        for (int i = threadIdx.x; i < 64 * 32; i += 256) {
            int r = i >> 5, k = i & 31;
            xs[r][k] = x[(size_t)(row0 + r) * FIN + k0 + k];
        }
        for (int i = threadIdx.x; i < 32 * 64; i += 256) {
            int k = i >> 6, c = i & 63;
            ws[k][c] = W1[(size_t)(k0 + k) * HD + c];
        }
        __syncthreads();
#pragma unroll 8
        for (int k = 0; k < 32; k++) {
            float a[4];
            float4 b4 = *(const float4*)&ws[k][4 * tx];
            float b[4] = {b4.x, b4.y, b4.z, b4.w};
#pragma unroll
            for (int i = 0; i < 4; i++) a[i] = xs[4 * ty + i][k];
#pragma unroll
            for (int i = 0; i < 4; i++)
#pragma unroll
                for (int j = 0; j < 4; j++) acc[i][j] += a[i] * b[j];
        }
        __syncthreads();
    }
#pragma unroll
    for (int i = 0; i < 4; i++) {
        float4 o = make_float4(acc[i][0], acc[i][1], acc[i][2], acc[i][3]);
        *(float4*)&g_xw[(size_t)(row0 + 4 * ty + i) * HD + 4 * tx] = o;
    }
}

// ---------------- aggregation: out[n] = (sum_{s in N(n)} in[s]*dinv[s] + in[n]*dinv[n]) * dinv[n] (+b, relu)
// One warp per node; lane covers 2 columns (float2). Gathers are 256B L2-hot rows.
__device__ __forceinline__ void agg_impl(const float* __restrict__ in,
                                         float* __restrict__ out,
                                         const float* __restrict__ bias,
                                         bool do_relu) {
    int gwarp = (blockIdx.x * blockDim.x + threadIdx.x) >> 5;
    int lane = threadIdx.x & 31;
    if (gwarp >= NN) return;
    int node = gwarp;
    float dn = g_dinv[node];

    float2 acc = *(const float2*)&in[(size_t)node * HD + lane * 2];
    acc.x *= dn; acc.y *= dn;  // self loop contribution (pre dinv[dst] factor)

    int beg = g_row_ptr[node], end = g_row_ptr[node + 1];
    for (int base = beg; base < end; base += 32) {
        int e = base + lane;
        int s = 0; float ds = 0.f;
        if (e < end) { s = g_col[e]; ds = g_dinv[s]; }
        int cnt = min(32, end - base);
        for (int j = 0; j < cnt; j++) {
            int   ss = __shfl_sync(0xffffffffu, s, j);
            float dd = __shfl_sync(0xffffffffu, ds, j);
            float2 v = *(const float2*)&in[(size_t)ss * HD + lane * 2];
            acc.x += v.x * dd;
            acc.y += v.y * dd;
        }
    }
    float bx = bias ? bias[lane * 2] : 0.f;
    float by = bias ? bias[lane * 2 + 1] : 0.f;
    float ox = acc.x * dn + bx;
    float oy = acc.y * dn + by;
    if (do_relu) { ox = fmaxf(ox, 0.f); oy = fmaxf(oy, 0.f); }
    *(float2*)&out[(size_t)node * HD + lane * 2] = make_float2(ox, oy);
}

__global__ void k_agg1(const float* __restrict__ b1) { agg_impl(g_xw, g_h, b1, true); }
__global__ void k_agg2()                             { agg_impl(g_h, g_m, nullptr, false); }

// ---------------- kernel 5: logits = M(8192x64) @ W2(64x8192) + b2, into d_out
// 128x128 tile, 256 threads, 8x8 per thread, K chunked by 32. ----------------
__global__ void k_gemm(const float* __restrict__ W2, const float* __restrict__ b2,
                       float* __restrict__ C) {
    __shared__ float Ms[32][132];  // [k][row] (transposed M tile)
    __shared__ float Ws[32][132];  // [k][col]
    int row0 = blockIdx.y * 128;
    int col0 = blockIdx.x * 128;
    int tx = threadIdx.x & 15, ty = threadIdx.x >> 4;
    float acc[8][8] = {};

    for (int k0 = 0; k0 < HD; k0 += 32) {
        // M tile: 128 rows x 32 k, via float4 (M row-major [NN][HD])
        for (int i4 = threadIdx.x; i4 < 1024; i4 += 256) {
            int r = i4 >> 3, kk = (i4 & 7) << 2;
            float4 v = *(const float4*)&g_m[(size_t)(row0 + r) * HD + k0 + kk];
            Ms[kk + 0][r] = v.x; Ms[kk + 1][r] = v.y;
            Ms[kk + 2][r] = v.z; Ms[kk + 3][r] = v.w;
        }
        // W2 tile: 32 k x 128 cols, coalesced float4
        for (int i4 = threadIdx.x; i4 < 1024; i4 += 256) {
            int k = i4 >> 5, cc = (i4 & 31) << 2;
            float4 v = *(const float4*)&W2[(size_t)(k0 + k) * NN + col0 + cc];
            *(float4*)&Ws[k][cc] = v;
        }
        __syncthreads();
#pragma unroll
        for (int k = 0; k < 32; k++) {
            float4 a0 = *(const float4*)&Ms[k][4 * ty];
            float4 a1 = *(const float4*)&Ms[k][64 + 4 * ty];
            float4 b0 = *(const float4*)&Ws[k][4 * tx];
            float4 b1 = *(const float4*)&Ws[k][64 + 4 * tx];
            float a[8] = {a0.x, a0.y, a0.z, a0.w, a1.x, a1.y, a1.z, a1.w};
            float b[8] = {b0.x, b0.y, b0.z, b0.w, b1.x, b1.y, b1.z, b1.w};
#pragma unroll
            for (int i = 0; i < 8; i++)
#pragma unroll
                for (int j = 0; j < 8; j++) acc[i][j] += a[i] * b[j];
        }
        __syncthreads();
    }

    float4 bb0 = *(const float4*)&b2[col0 + 4 * tx];
    float4 bb1 = *(const float4*)&b2[col0 + 64 + 4 * tx];
#pragma unroll
    for (int i = 0; i < 8; i++) {
        int r = row0 + ((i < 4) ? (4 * ty + i) : (64 + 4 * ty + (i - 4)));
        float4 o0 = make_float4(acc[i][0] + bb0.x, acc[i][1] + bb0.y,
                                acc[i][2] + bb0.z, acc[i][3] + bb0.w);
        float4 o1 = make_float4(acc[i][4] + bb1.x, acc[i][5] + bb1.y,
                                acc[i][6] + bb1.z, acc[i][7] + bb1.w);
        *(float4*)&C[(size_t)r * NN + col0 + 4 * tx] = o0;
        *(float4*)&C[(size_t)r * NN + col0 + 64 + 4 * tx] = o1;
    }
}

// ---------------- kernel 6: in-place log_softmax per row ----------------
// One block (256 threads) per row; row lives in registers (8 float4 / thread).
__global__ void k_logsoftmax(float* __restrict__ C) {
    size_t row = blockIdx.x;
    float4* p4 = (float4*)(C + row * NN);
    int t = threadIdx.x;
    float4 v[8];
    float m = -1e30f;
#pragma unroll
    for (int j = 0; j < 8; j++) {
        v[j] = p4[j * 256 + t];
        m = fmaxf(m, fmaxf(fmaxf(v[j].x, v[j].y), fmaxf(v[j].z, v[j].w)));
    }
    __shared__ float red[8];
    int lane = t & 31, wid = t >> 5;
#pragma unroll
    for (int off = 16; off > 0; off >>= 1)
        m = fmaxf(m, __shfl_xor_sync(0xffffffffu, m, off));
    if (lane == 0) red[wid] = m;
    __syncthreads();
    if (t == 0) {
        float mm = red[0];
#pragma unroll
        for (int i = 1; i < 8; i++) mm = fmaxf(mm, red[i]);
        red[0] = mm;
    }
    __syncthreads();
    m = red[0];
    __syncthreads();

    float s = 0.f;
#pragma unroll
    for (int j = 0; j < 8; j++)
        s += __expf(v[j].x - m) + __expf(v[j].y - m) +
             __expf(v[j].z - m) + __expf(v[j].w - m);
#pragma unroll
    for (int off = 16; off > 0; off >>= 1)
        s += __shfl_xor_sync(0xffffffffu, s, off);
    if (lane == 0) red[wid] = s;
    __syncthreads();
    if (t == 0) {
        float ss = 0.f;
#pragma unroll
        for (int i = 0; i < 8; i++) ss += red[i];
        red[0] = ss;
    }
    __syncthreads();
    float lz = m + __logf(red[0]);

#pragma unroll
    for (int j = 0; j < 8; j++) {
        float4 o = make_float4(v[j].x - lz, v[j].y - lz, v[j].z - lz, v[j].w - lz);
        p4[j * 256 + t] = o;
    }
}

// ---------------- launch ----------------
extern "C" void kernel_launch(void* const* d_in, const int* in_sizes, int n_in,
                              void* d_out, int out_size) {
    const float* x  = (const float*)d_in[0];
    const void*  ei = d_in[1];                 // edge_index [2, E] (int32 or int64)
    const float* W1 = (const float*)d_in[2];
    const float* b1 = (const float*)d_in[3];
    const float* W2 = (const float*)d_in[4];
    const float* b2 = (const float*)d_in[5];
    float* out = (float*)d_out;

    int E = in_sizes[1] / 2;  // element count of edge_index is 2*E
    int eblocks = (E + 255) / 256;

    k_init_detect<<<NN / 256, 256>>>((const int*)ei);
    k_hist<<<eblocks, 256>>>(ei, E);
    k_scan<<<1, 1024>>>();
    k_scatter<<<eblocks, 256>>>(ei, E);
    k_xw<<<NN / 64, 256>>>(x, W1);
    k_agg1<<<NN / 8, 256>>>(b1);
    k_agg2<<<NN / 8, 256>>>();
    dim3 gg(NN / 128, NN / 128);
    k_gemm<<<gg, 256>>>(W2, b2, out);
    k_logsoftmax<<<NN, 256>>>(out);
}

// round 4
// speedup vs baseline: 1.1766x; 1.1766x over previous
#include <cuda_runtime.h>
#include <cuda_bf16.h>
#include <math.h>
#include <stdint.h>

// Problem constants (fixed shapes for this problem)
#define NN   8192      // nodes (= output classes)
#define FIN  512       // input features
#define HD   64        // hidden dim
#define MAXE (NN * 64) // edges
#define NCB  64        // number of 128-wide column blocks in the big GEMM

// ---------------- device scratch (static allocation; no cudaMalloc) ----------------
__device__ int   g_is64;             // edge_index dtype flag (1 = int64, 0 = int32)
__device__ int   g_hist[NN];         // in-degree histogram (dst counts)
__device__ int   g_row_ptr[NN + 1];  // CSR row pointers (by dst)
__device__ int   g_cursor[NN];       // scatter cursors
__device__ int   g_col[MAXE];        // CSR column (src) indices
__device__ float g_dinv[NN];         // deg^{-1/2} (deg includes self loop)
__device__ float g_xw[NN * HD];      // x @ W1
__device__ float g_h[NN * HD];       // layer-1 output (post relu)
__device__ float g_m[NN * HD];       // Â h  (layer-2 aggregated hidden)

// bf16x2 split operands for the tensor-core GEMM
__device__ __nv_bfloat16 g_mh[NN * HD],  g_ml[NN * HD];   // M hi/lo
__device__ __nv_bfloat16 g_w2h[HD * NN], g_w2l[HD * NN];  // W2 hi/lo

// per-(colblock,row) online softmax stats + final log-normalizer
__device__ float g_pmax[NCB * NN];
__device__ float g_psum[NCB * NN];
__device__ float g_lz[NN];

// ---------------- helpers ----------------
__device__ __forceinline__ int edge_val(const void* ei, long long i) {
    if (g_is64) return (int)((const long long*)ei)[i];
    return ((const int*)ei)[i];
}

__device__ __forceinline__ void ldsm4(uint32_t* r, uint32_t addr) {
    asm volatile("ldmatrix.sync.aligned.m8n8.x4.shared.b16 {%0,%1,%2,%3}, [%4];"
                 : "=r"(r[0]), "=r"(r[1]), "=r"(r[2]), "=r"(r[3]) : "r"(addr));
}
__device__ __forceinline__ void ldsm4t(uint32_t* r, uint32_t addr) {
    asm volatile("ldmatrix.sync.aligned.m8n8.x4.trans.shared.b16 {%0,%1,%2,%3}, [%4];"
                 : "=r"(r[0]), "=r"(r[1]), "=r"(r[2]), "=r"(r[3]) : "r"(addr));
}
__device__ __forceinline__ void mma16816(float* c, const uint32_t* a, const uint32_t* b) {
    asm volatile("mma.sync.aligned.m16n8k16.row.col.f32.bf16.bf16.f32 "
                 "{%0,%1,%2,%3}, {%4,%5,%6,%7}, {%8,%9}, {%0,%1,%2,%3};"
                 : "+f"(c[0]), "+f"(c[1]), "+f"(c[2]), "+f"(c[3])
                 : "r"(a[0]), "r"(a[1]), "r"(a[2]), "r"(a[3]), "r"(b[0]), "r"(b[1]));
}

// ---------------- kernel 0: zero counters + detect int width ----------------
__global__ void k_init_detect(const int* eiw) {
    int t = blockIdx.x * blockDim.x + threadIdx.x;
    if (t < NN) { g_hist[t] = 0; g_cursor[t] = 0; }
    if (blockIdx.x == 0) {
        __shared__ int cnt;
        if (threadIdx.x == 0) cnt = 0;
        __syncthreads();
        int c = 0;
        for (int i = threadIdx.x; i < 1024; i += blockDim.x)
            if (eiw[2 * i + 1] == 0) c++;
        atomicAdd(&cnt, c);
        __syncthreads();
        if (threadIdx.x == 0) g_is64 = (cnt > 900) ? 1 : 0;
    }
}

// ---------------- kernel 1: histogram of dst ----------------
__global__ void k_hist(const void* ei, int E) {
    int e = blockIdx.x * blockDim.x + threadIdx.x;
    if (e < E) {
        int d = edge_val(ei, (long long)E + e);
        atomicAdd(&g_hist[d], 1);
    }
}

// ---------------- kernel 2: exclusive scan + dinv ----------------
__global__ void k_scan() {
    int t = threadIdx.x;
    int vals[8];
    int tsum = 0;
#pragma unroll
    for (int j = 0; j < 8; j++) { vals[j] = g_hist[t * 8 + j]; tsum += vals[j]; }

    int lane = t & 31, wid = t >> 5;
    int incl = tsum;
#pragma unroll
    for (int off = 1; off < 32; off <<= 1) {
        int v = __shfl_up_sync(0xffffffffu, incl, off);
        if (lane >= off) incl += v;
    }
    __shared__ int wsum[32];
    if (lane == 31) wsum[wid] = incl;
    __syncthreads();
    if (wid == 0) {
        int v = wsum[lane];
        int iv = v;
#pragma unroll
        for (int off = 1; off < 32; off <<= 1) {
            int u = __shfl_up_sync(0xffffffffu, iv, off);
            if (lane >= off) iv += u;
        }
        wsum[lane] = iv - v;
    }
    __syncthreads();
    int run = wsum[wid] + (incl - tsum);
#pragma unroll
    for (int j = 0; j < 8; j++) {
        int idx = t * 8 + j;
        g_row_ptr[idx] = run;
        g_dinv[idx] = rsqrtf((float)vals[j] + 1.0f);
        run += vals[j];
    }
    if (t == 1023) g_row_ptr[NN] = run;
}

// ---------------- kernel 3: scatter src into CSR ----------------
__global__ void k_scatter(const void* ei, int E) {
    int e = blockIdx.x * blockDim.x + threadIdx.x;
    if (e < E) {
        int s = edge_val(ei, e);
        int d = edge_val(ei, (long long)E + e);
        int pos = g_row_ptr[d] + atomicAdd(&g_cursor[d], 1);
        g_col[pos] = s;
    }
}

// ---------------- kernel 4: XW = x(8192x512) @ W1(512x64) ----------------
__global__ void k_xw(const float* __restrict__ x, const float* __restrict__ W1) {
    __shared__ float xs[64][33];
    __shared__ float ws[32][64];
    int row0 = blockIdx.x * 64;
    int tx = threadIdx.x & 15, ty = threadIdx.x >> 4;
    float acc[4][4] = {};
    for (int k0 = 0; k0 < FIN; k0 += 32) {
        for (int i = threadIdx.x; i < 64 * 32; i += 256) {
            int r = i >> 5, k = i & 31;
            xs[r][k] = x[(size_t)(row0 + r) * FIN + k0 + k];
        }
        for (int i = threadIdx.x; i < 32 * 64; i += 256) {
            int k = i >> 6, c = i & 63;
            ws[k][c] = W1[(size_t)(k0 + k) * HD + c];
        }
        __syncthreads();
#pragma unroll 8
        for (int k = 0; k < 32; k++) {
            float a[4];
            float4 b4 = *(const float4*)&ws[k][4 * tx];
            float b[4] = {b4.x, b4.y, b4.z, b4.w};
#pragma unroll
            for (int i = 0; i < 4; i++) a[i] = xs[4 * ty + i][k];
#pragma unroll
            for (int i = 0; i < 4; i++)
#pragma unroll
                for (int j = 0; j < 4; j++) acc[i][j] += a[i] * b[j];
        }
        __syncthreads();
    }
#pragma unroll
    for (int i = 0; i < 4; i++) {
        float4 o = make_float4(acc[i][0], acc[i][1], acc[i][2], acc[i][3]);
        *(float4*)&g_xw[(size_t)(row0 + 4 * ty + i) * HD + 4 * tx] = o;
    }
}

// ---------------- aggregation ----------------
__device__ __forceinline__ void agg_impl(const float* __restrict__ in,
                                         float* __restrict__ out,
                                         const float* __restrict__ bias,
                                         bool do_relu) {
    int gwarp = (blockIdx.x * blockDim.x + threadIdx.x) >> 5;
    int lane = threadIdx.x & 31;
    if (gwarp >= NN) return;
    int node = gwarp;
    float dn = g_dinv[node];

    float2 acc = *(const float2*)&in[(size_t)node * HD + lane * 2];
    acc.x *= dn; acc.y *= dn;

    int beg = g_row_ptr[node], end = g_row_ptr[node + 1];
    for (int base = beg; base < end; base += 32) {
        int e = base + lane;
        int s = 0; float ds = 0.f;
        if (e < end) { s = g_col[e]; ds = g_dinv[s]; }
        int cnt = min(32, end - base);
        for (int j = 0; j < cnt; j++) {
            int   ss = __shfl_sync(0xffffffffu, s, j);
            float dd = __shfl_sync(0xffffffffu, ds, j);
            float2 v = *(const float2*)&in[(size_t)ss * HD + lane * 2];
            acc.x += v.x * dd;
            acc.y += v.y * dd;
        }
    }
    float bx = bias ? bias[lane * 2] : 0.f;
    float by = bias ? bias[lane * 2 + 1] : 0.f;
    float ox = acc.x * dn + bx;
    float oy = acc.y * dn + by;
    if (do_relu) { ox = fmaxf(ox, 0.f); oy = fmaxf(oy, 0.f); }
    *(float2*)&out[(size_t)node * HD + lane * 2] = make_float2(ox, oy);
}

__global__ void k_agg1(const float* __restrict__ b1) { agg_impl(g_xw, g_h, b1, true); }
__global__ void k_agg2()                             { agg_impl(g_h, g_m, nullptr, false); }

// ---------------- kernel 5: split M and W2 into bf16 hi/lo ----------------
__global__ void k_convert(const float* __restrict__ W2) {
    int i = blockIdx.x * blockDim.x + threadIdx.x;
    if (i < NN * HD) {
        float v = g_m[i];
        __nv_bfloat16 h = __float2bfloat16(v);
        g_mh[i] = h;
        g_ml[i] = __float2bfloat16(v - __bfloat162float(h));
        float w = W2[i];
        __nv_bfloat16 wh = __float2bfloat16(w);
        g_w2h[i] = wh;
        g_w2l[i] = __float2bfloat16(w - __bfloat162float(wh));
    }
}

// ---------------- kernel 6: bf16x2 MMA GEMM, 128x128 tile, 8 warps ----------------
// WRITE=false: compute logits tile, emit per-(colblock,row) (max, sumexp) only.
// WRITE=true : recompute, write  acc + b2[col] - lz[row]  to C.
// Dynamic smem layout (73728 bytes requested):
//   Ah [128][72] bf16 @0       (stride 144B, padded for conflict-free LDSM)
//   Al [128][72] bf16 @18432
//   Bh [64][136] bf16 @36864   (stride 272B)
//   Bl [64][136] bf16 @54272
//   sB2 [128] f32    @71680
//   sLz [128] f32    @72192
// Stats overlay (after syncthreads): sMax[128*4], sSum[128*4] @0.
template <bool WRITE>
__global__ __launch_bounds__(256) void k_mma(const float* __restrict__ b2,
                                             float* __restrict__ C) {
    extern __shared__ char sm[];
    __nv_bfloat16* Ah = (__nv_bfloat16*)sm;
    __nv_bfloat16* Al = (__nv_bfloat16*)(sm + 18432);
    __nv_bfloat16* Bh = (__nv_bfloat16*)(sm + 36864);
    __nv_bfloat16* Bl = (__nv_bfloat16*)(sm + 54272);
    float* sB2 = (float*)(sm + 71680);
    float* sLz = (float*)(sm + 72192);

    int tid = threadIdx.x;
    int row0 = blockIdx.y * 128, col0 = blockIdx.x * 128;

    // load A (M rows, bf16 hi/lo), rows are 128B -> 8 uint4 each
    for (int i = tid; i < 1024; i += 256) {
        int r = i >> 3, q = i & 7;
        *(uint4*)((char*)Ah + r * 144 + q * 16) =
            *(const uint4*)((const char*)(g_mh + (size_t)(row0 + r) * HD) + q * 16);
        *(uint4*)((char*)Al + r * 144 + q * 16) =
            *(const uint4*)((const char*)(g_ml + (size_t)(row0 + r) * HD) + q * 16);
    }
    // load B (W2 tile 64 x 128, bf16 hi/lo), rows are 256B -> 16 uint4 each
    for (int i = tid; i < 1024; i += 256) {
        int r = i >> 4, q = i & 15;
        *(uint4*)((char*)Bh + r * 272 + q * 16) =
            *(const uint4*)((const char*)(g_w2h + (size_t)r * NN + col0) + q * 16);
        *(uint4*)((char*)Bl + r * 272 + q * 16) =
            *(const uint4*)((const char*)(g_w2l + (size_t)r * NN + col0) + q * 16);
    }
    if (tid < 128) {
        sB2[tid] = b2[col0 + tid];
        if (WRITE) sLz[tid] = g_lz[row0 + tid];
    }
    __syncthreads();

    int lane = tid & 31, wid = tid >> 5;
    int wr = wid >> 2, wc = wid & 3;      // warp tile: rows [wr*64,+64), cols [wc*32,+32)
    int g = lane >> 2, t4 = lane & 3;

    float c[4][4][4];
#pragma unroll
    for (int a = 0; a < 4; a++)
#pragma unroll
        for (int b = 0; b < 4; b++)
#pragma unroll
            for (int d = 0; d < 4; d++) c[a][b][d] = 0.f;

    uint32_t ah_base = (uint32_t)__cvta_generic_to_shared(Ah);
    uint32_t al_base = (uint32_t)__cvta_generic_to_shared(Al);
    uint32_t bh_base = (uint32_t)__cvta_generic_to_shared(Bh);
    uint32_t bl_base = (uint32_t)__cvta_generic_to_shared(Bl);

    int ra = (lane & 7) + ((lane & 8) ? 8 : 0);
    int ka_off = (lane & 16) ? 8 : 0;
    int rb = (lane & 7) + ((lane & 8) ? 8 : 0);
    int nb_off = (lane & 16) ? 8 : 0;

#pragma unroll
    for (int ks = 0; ks < 4; ks++) {
        int k0 = ks * 16;
        uint32_t ahf[4][4], alf[4][4];
#pragma unroll
        for (int mi = 0; mi < 4; mi++) {
            uint32_t off = (uint32_t)((wr * 64 + mi * 16 + ra) * 144 + (k0 + ka_off) * 2);
            ldsm4(ahf[mi], ah_base + off);
            ldsm4(alf[mi], al_base + off);
        }
        uint32_t bhf[4][2], blf[4][2];
#pragma unroll
        for (int p = 0; p < 2; p++) {
            uint32_t off = (uint32_t)((k0 + rb) * 272 + (wc * 32 + p * 16 + nb_off) * 2);
            uint32_t r[4];
            ldsm4t(r, bh_base + off);
            bhf[2 * p][0] = r[0]; bhf[2 * p][1] = r[1];
            bhf[2 * p + 1][0] = r[2]; bhf[2 * p + 1][1] = r[3];
            ldsm4t(r, bl_base + off);
            blf[2 * p][0] = r[0]; blf[2 * p][1] = r[1];
            blf[2 * p + 1][0] = r[2]; blf[2 * p + 1][1] = r[3];
        }
#pragma unroll
        for (int mi = 0; mi < 4; mi++)
#pragma unroll
            for (int nj = 0; nj < 4; nj++) {
                mma16816(c[mi][nj], ahf[mi], bhf[nj]);
                mma16816(c[mi][nj], ahf[mi], blf[nj]);
                mma16816(c[mi][nj], alf[mi], bhf[nj]);
            }
    }

    if (WRITE) {
#pragma unroll
        for (int mi = 0; mi < 4; mi++)
#pragma unroll
            for (int h = 0; h < 2; h++) {
                int rl = wr * 64 + mi * 16 + g + 8 * h;
                float lz = sLz[rl];
                size_t rowbase = (size_t)(row0 + rl) * NN + col0;
#pragma unroll
                for (int nj = 0; nj < 4; nj++) {
                    int cl = wc * 32 + nj * 8 + 2 * t4;
                    float2 o;
                    o.x = c[mi][nj][2 * h]     + sB2[cl]     - lz;
                    o.y = c[mi][nj][2 * h + 1] + sB2[cl + 1] - lz;
                    *(float2*)&C[rowbase + cl] = o;
                }
            }
    } else {
        __syncthreads();  // done reading A/B smem; overlay with stats
        float* sMax = (float*)sm;
        float* sSum = sMax + 512;
#pragma unroll
        for (int mi = 0; mi < 4; mi++)
#pragma unroll
            for (int h = 0; h < 2; h++) {
                int rl = wr * 64 + mi * 16 + g + 8 * h;
                float v[8];
                float m = -1e30f;
#pragma unroll
                for (int nj = 0; nj < 4; nj++) {
                    int cl = wc * 32 + nj * 8 + 2 * t4;
                    v[2 * nj]     = c[mi][nj][2 * h]     + sB2[cl];
                    v[2 * nj + 1] = c[mi][nj][2 * h + 1] + sB2[cl + 1];
                    m = fmaxf(m, fmaxf(v[2 * nj], v[2 * nj + 1]));
                }
                m = fmaxf(m, __shfl_xor_sync(0xffffffffu, m, 1));
                m = fmaxf(m, __shfl_xor_sync(0xffffffffu, m, 2));
                float s = 0.f;
#pragma unroll
                for (int q = 0; q < 8; q++) s += __expf(v[q] - m);
                s += __shfl_xor_sync(0xffffffffu, s, 1);
                s += __shfl_xor_sync(0xffffffffu, s, 2);
                if (t4 == 0) { sMax[rl * 4 + wc] = m; sSum[rl * 4 + wc] = s; }
            }
        __syncthreads();
        if (tid < 128) {
            float m = -1e30f;
#pragma unroll
            for (int w = 0; w < 4; w++) m = fmaxf(m, sMax[tid * 4 + w]);
            float s = 0.f;
#pragma unroll
            for (int w = 0; w < 4; w++) s += sSum[tid * 4 + w] * __expf(sMax[tid * 4 + w] - m);
            g_pmax[blockIdx.x * NN + row0 + tid] = m;
            g_psum[blockIdx.x * NN + row0 + tid] = s;
        }
    }
}

// ---------------- kernel 7: merge per-colblock stats into lz[row] ----------------
__global__ void k_reduce_lz() {
    int row = blockIdx.x * blockDim.x + threadIdx.x;
    if (row >= NN) return;
    float m = -1e30f;
#pragma unroll 8
    for (int cb = 0; cb < NCB; cb++) m = fmaxf(m, g_pmax[cb * NN + row]);
    float s = 0.f;
#pragma unroll 8
    for (int cb = 0; cb < NCB; cb++)
        s += g_psum[cb * NN + row] * __expf(g_pmax[cb * NN + row] - m);
    g_lz[row] = m + __logf(s);
}

// ---------------- launch ----------------
extern "C" void kernel_launch(void* const* d_in, const int* in_sizes, int n_in,
                              void* d_out, int out_size) {
    const float* x  = (const float*)d_in[0];
    const void*  ei = d_in[1];
    const float* W1 = (const float*)d_in[2];
    const float* b1 = (const float*)d_in[3];
    const float* W2 = (const float*)d_in[4];
    const float* b2 = (const float*)d_in[5];
    float* out = (float*)d_out;

    int E = in_sizes[1] / 2;
    int eblocks = (E + 255) / 256;

    cudaFuncSetAttribute((const void*)k_mma<false>,
                         cudaFuncAttributeMaxDynamicSharedMemorySize, 73728);
    cudaFuncSetAttribute((const void*)k_mma<true>,
                         cudaFuncAttributeMaxDynamicSharedMemorySize, 73728);

    k_init_detect<<<NN / 256, 256>>>((const int*)ei);
    k_hist<<<eblocks, 256>>>(ei, E);
    k_scan<<<1, 1024>>>();
    k_scatter<<<eblocks, 256>>>(ei, E);
    k_xw<<<NN / 64, 256>>>(x, W1);
    k_agg1<<<NN / 8, 256>>>(b1);
    k_agg2<<<NN / 8, 256>>>();
    k_convert<<<(NN * HD + 511) / 512, 512>>>(W2);

    dim3 gg(NCB, NN / 128);
    k_mma<false><<<gg, 256, 73728>>>(b2, nullptr);   // stats pass
    k_reduce_lz<<<NN / 256, 256>>>();
    k_mma<true><<<gg, 256, 73728>>>(b2, out);        // write pass
}

// round 10
// speedup vs baseline: 1.5269x; 1.2977x over previous
#include <cuda_runtime.h>
#include <cuda_fp16.h>
#include <math.h>
#include <stdint.h>

// Problem constants (fixed shapes for this problem)
#define NN   8192      // nodes (= output classes)
#define FIN  512       // input features
#define HD   64        // hidden dim
#define MAXE (NN * 64) // edges
#define NCB  64        // number of 128-wide column blocks in the big GEMM

// ---------------- device scratch (static allocation; no cudaMalloc) ----------------
__device__ int   g_is64;             // edge_index dtype flag (1 = int64, 0 = int32)
__device__ int   g_hist[NN];         // in-degree histogram (dst counts)
__device__ int   g_row_ptr[NN + 1];  // CSR row pointers (by dst)
__device__ int   g_cursor[NN];       // scatter cursors
__device__ int   g_col[MAXE];        // CSR column (src) indices
__device__ float g_dinv[NN];         // deg^{-1/2} (deg includes self loop)
__device__ float g_xw[NN * HD];      // x @ W1
__device__ float g_h[NN * HD];       // layer-1 output (post relu)
__device__ float g_m[NN * HD];       // Â h  (layer-2 aggregated hidden)

// fp16 operands for the tensor-core GEMM
__device__ __half g_m16[NN * HD];    // M in fp16, row-major [NN][HD]
__device__ __half g_w216[HD * NN];   // W2 in fp16, row-major [HD][NN]

// per-(colblock,row) online softmax stats + final log-normalizer
__device__ float g_pmax[NCB * NN];
__device__ float g_psum[NCB * NN];
__device__ float g_lz[NN];

// ---------------- helpers ----------------
__device__ __forceinline__ int edge_val(const void* ei, long long i) {
    if (g_is64) return (int)((const long long*)ei)[i];
    return ((const int*)ei)[i];
}

__device__ __forceinline__ void ldsm4(uint32_t* r, uint32_t addr) {
    asm volatile("ldmatrix.sync.aligned.m8n8.x4.shared.b16 {%0,%1,%2,%3}, [%4];"
                 : "=r"(r[0]), "=r"(r[1]), "=r"(r[2]), "=r"(r[3]) : "r"(addr));
}
__device__ __forceinline__ void ldsm4t(uint32_t* r, uint32_t addr) {
    asm volatile("ldmatrix.sync.aligned.m8n8.x4.trans.shared.b16 {%0,%1,%2,%3}, [%4];"
                 : "=r"(r[0]), "=r"(r[1]), "=r"(r[2]), "=r"(r[3]) : "r"(addr));
}
__device__ __forceinline__ void mma16816(float* c, const uint32_t* a, const uint32_t* b) {
    asm volatile("mma.sync.aligned.m16n8k16.row.col.f32.f16.f16.f32 "
                 "{%0,%1,%2,%3}, {%4,%5,%6,%7}, {%8,%9}, {%0,%1,%2,%3};"
                 : "+f"(c[0]), "+f"(c[1]), "+f"(c[2]), "+f"(c[3])
                 : "r"(a[0]), "r"(a[1]), "r"(a[2]), "r"(a[3]), "r"(b[0]), "r"(b[1]));
}

// ---------------- kernel 0: zero counters + detect int width ----------------
__global__ void k_init_detect(const int* eiw) {
    int t = blockIdx.x * blockDim.x + threadIdx.x;
    if (t < NN) { g_hist[t] = 0; g_cursor[t] = 0; }
    if (blockIdx.x == 0) {
        __shared__ int cnt;
        if (threadIdx.x == 0) cnt = 0;
        __syncthreads();
        int c = 0;
        for (int i = threadIdx.x; i < 1024; i += blockDim.x)
            if (eiw[2 * i + 1] == 0) c++;
        atomicAdd(&cnt, c);
        __syncthreads();
        if (threadIdx.x == 0) g_is64 = (cnt > 900) ? 1 : 0;
    }
}

// ---------------- kernel 1: histogram of dst ----------------
__global__ void k_hist(const void* ei, int E) {
    int e = blockIdx.x * blockDim.x + threadIdx.x;
    if (e < E) {
        int d = edge_val(ei, (long long)E + e);
        atomicAdd(&g_hist[d], 1);
    }
}

// ---------------- kernel 2: exclusive scan + dinv ----------------
__global__ void k_scan() {
    int t = threadIdx.x;
    int vals[8];
    int tsum = 0;
#pragma unroll
    for (int j = 0; j < 8; j++) { vals[j] = g_hist[t * 8 + j]; tsum += vals[j]; }

    int lane = t & 31, wid = t >> 5;
    int incl = tsum;
#pragma unroll
    for (int off = 1; off < 32; off <<= 1) {
        int v = __shfl_up_sync(0xffffffffu, incl, off);
        if (lane >= off) incl += v;
    }
    __shared__ int wsum[32];
    if (lane == 31) wsum[wid] = incl;
    __syncthreads();
    if (wid == 0) {
        int v = wsum[lane];
        int iv = v;
#pragma unroll
        for (int off = 1; off < 32; off <<= 1) {
            int u = __shfl_up_sync(0xffffffffu, iv, off);
            if (lane >= off) iv += u;
        }
        wsum[lane] = iv - v;
    }
    __syncthreads();
    int run = wsum[wid] + (incl - tsum);
#pragma unroll
    for (int j = 0; j < 8; j++) {
        int idx = t * 8 + j;
        g_row_ptr[idx] = run;
        g_dinv[idx] = rsqrtf((float)vals[j] + 1.0f);
        run += vals[j];
    }
    if (t == 1023) g_row_ptr[NN] = run;
}

// ---------------- kernel 3: scatter src into CSR ----------------
__global__ void k_scatter(const void* ei, int E) {
    int e = blockIdx.x * blockDim.x + threadIdx.x;
    if (e < E) {
        int s = edge_val(ei, e);
        int d = edge_val(ei, (long long)E + e);
        int pos = g_row_ptr[d] + atomicAdd(&g_cursor[d], 1);
        g_col[pos] = s;
    }
}

// ---------------- kernel 4: XW = x(8192x512) @ W1(512x64) ----------------
__global__ void k_xw(const float* __restrict__ x, const float* __restrict__ W1) {
    __shared__ float xs[64][33];
    __shared__ float ws[32][64];
    int row0 = blockIdx.x * 64;
    int tx = threadIdx.x & 15, ty = threadIdx.x >> 4;
    float acc[4][4] = {};
    for (int k0 = 0; k0 < FIN; k0 += 32) {
        for (int i = threadIdx.x; i < 64 * 32; i += 256) {
            int r = i >> 5, k = i & 31;
            xs[r][k] = x[(size_t)(row0 + r) * FIN + k0 + k];
        }
        for (int i = threadIdx.x; i < 32 * 64; i += 256) {
            int k = i >> 6, c = i & 63;
            ws[k][c] = W1[(size_t)(k0 + k) * HD + c];
        }
        __syncthreads();
#pragma unroll 8
        for (int k = 0; k < 32; k++) {
            float a[4];
            float4 b4 = *(const float4*)&ws[k][4 * tx];
            float b[4] = {b4.x, b4.y, b4.z, b4.w};
#pragma unroll
            for (int i = 0; i < 4; i++) a[i] = xs[4 * ty + i][k];
#pragma unroll
            for (int i = 0; i < 4; i++)
#pragma unroll
                for (int j = 0; j < 4; j++) acc[i][j] += a[i] * b[j];
        }
        __syncthreads();
    }
#pragma unroll
    for (int i = 0; i < 4; i++) {
        float4 o = make_float4(acc[i][0], acc[i][1], acc[i][2], acc[i][3]);
        *(float4*)&g_xw[(size_t)(row0 + 4 * ty + i) * HD + 4 * tx] = o;
    }
}

// ---------------- aggregation ----------------
__device__ __forceinline__ void agg_impl(const float* __restrict__ in,
                                         float* __restrict__ out,
                                         const float* __restrict__ bias,
                                         bool do_relu) {
    int gwarp = (blockIdx.x * blockDim.x + threadIdx.x) >> 5;
    int lane = threadIdx.x & 31;
    if (gwarp >= NN) return;
    int node = gwarp;
    float dn = g_dinv[node];

    float2 acc = *(const float2*)&in[(size_t)node * HD + lane * 2];
    acc.x *= dn; acc.y *= dn;

    int beg = g_row_ptr[node], end = g_row_ptr[node + 1];
    for (int base = beg; base < end; base += 32) {
        int e = base + lane;
        int s = 0; float ds = 0.f;
        if (e < end) { s = g_col[e]; ds = g_dinv[s]; }
        int cnt = min(32, end - base);
        for (int j = 0; j < cnt; j++) {
            int   ss = __shfl_sync(0xffffffffu, s, j);
            float dd = __shfl_sync(0xffffffffu, ds, j);
            float2 v = *(const float2*)&in[(size_t)ss * HD + lane * 2];
            acc.x += v.x * dd;
            acc.y += v.y * dd;
        }
    }
    float bx = bias ? bias[lane * 2] : 0.f;
    float by = bias ? bias[lane * 2 + 1] : 0.f;
    float ox = acc.x * dn + bx;
    float oy = acc.y * dn + by;
    if (do_relu) { ox = fmaxf(ox, 0.f); oy = fmaxf(oy, 0.f); }
    *(float2*)&out[(size_t)node * HD + lane * 2] = make_float2(ox, oy);
}

__global__ void k_agg1(const float* __restrict__ b1) { agg_impl(g_xw, g_h, b1, true); }
__global__ void k_agg2()                             { agg_impl(g_h, g_m, nullptr, false); }

// ---------------- kernel 5: convert M and W2 to fp16 ----------------
__global__ void k_convert(const float* __restrict__ W2) {
    int i = blockIdx.x * blockDim.x + threadIdx.x;   // over NN*HD/4
    float4 m4 = *(const float4*)&g_m[4 * i];
    float4 w4 = *(const float4*)&W2[4 * i];
    __half2* mo = (__half2*)g_m16;
    __half2* wo = (__half2*)g_w216;
    mo[2 * i]     = __floats2half2_rn(m4.x, m4.y);
    mo[2 * i + 1] = __floats2half2_rn(m4.z, m4.w);
    wo[2 * i]     = __floats2half2_rn(w4.x, w4.y);
    wo[2 * i + 1] = __floats2half2_rn(w4.z, w4.w);
}

// ---------------- kernel 6: fp16 MMA GEMM, 128x128 tile, 8 warps ----------------
// WRITE=false: compute logits tile, emit per-(colblock,row) (max, sumexp) only.
// WRITE=true : recompute, write  acc + b2[col] - lz[row]  to C.
template <bool WRITE>
__global__ __launch_bounds__(256) void k_mma(const float* __restrict__ b2,
                                             float* __restrict__ C) {
    __shared__ __align__(16) __half Ah[128][72];   // [row][k], 144B stride
    __shared__ __align__(16) __half Bh[64][136];   // [k][col], 272B stride
    __shared__ float sB2[128];
    __shared__ float sLz[128];
    __shared__ float sMax[512];
    __shared__ float sSum[512];

    int tid = threadIdx.x;
    int row0 = blockIdx.y * 128, col0 = blockIdx.x * 128;

    // load A (M rows fp16), rows are 128B -> 8 uint4 each
    for (int i = tid; i < 1024; i += 256) {
        int r = i >> 3, q = i & 7;
        *(uint4*)((char*)&Ah[r][0] + q * 16) =
            *(const uint4*)((const char*)(g_m16 + (size_t)(row0 + r) * HD) + q * 16);
    }
    // load B (W2 tile 64 x 128 fp16), rows are 256B -> 16 uint4 each
    for (int i = tid; i < 1024; i += 256) {
        int r = i >> 4, q = i & 15;
        *(uint4*)((char*)&Bh[r][0] + q * 16) =
            *(const uint4*)((const char*)(g_w216 + (size_t)r * NN + col0) + q * 16);
    }
    if (tid < 128) {
        sB2[tid] = b2[col0 + tid];
        if (WRITE) sLz[tid] = g_lz[row0 + tid];
    }
    __syncthreads();

    int lane = tid & 31, wid = tid >> 5;
    int wr = wid >> 2, wc = wid & 3;      // warp tile: rows [wr*64,+64), cols [wc*32,+32)
    int g = lane >> 2, t4 = lane & 3;

    float c[4][4][4];
#pragma unroll
    for (int a = 0; a < 4; a++)
#pragma unroll
        for (int b = 0; b < 4; b++)
#pragma unroll
            for (int d = 0; d < 4; d++) c[a][b][d] = 0.f;

    uint32_t ah_base = (uint32_t)__cvta_generic_to_shared(&Ah[0][0]);
    uint32_t bh_base = (uint32_t)__cvta_generic_to_shared(&Bh[0][0]);

    int ra = (lane & 7) + ((lane & 8) ? 8 : 0);
    int ka_off = (lane & 16) ? 8 : 0;
    int rb = (lane & 7) + ((lane & 8) ? 8 : 0);
    int nb_off = (lane & 16) ? 8 : 0;

#pragma unroll
    for (int ks = 0; ks < 4; ks++) {
        int k0 = ks * 16;
        uint32_t ahf[4][4];
#pragma unroll
        for (int mi = 0; mi < 4; mi++) {
            uint32_t off = (uint32_t)((wr * 64 + mi * 16 + ra) * 144 + (k0 + ka_off) * 2);
            ldsm4(ahf[mi], ah_base + off);
        }
        uint32_t bhf[4][2];
#pragma unroll
        for (int p = 0; p < 2; p++) {
            uint32_t off = (uint32_t)((k0 + rb) * 272 + (wc * 32 + p * 16 + nb_off) * 2);
            uint32_t r[4];
            ldsm4t(r, bh_base + off);
            bhf[2 * p][0] = r[0]; bhf[2 * p][1] = r[1];
            bhf[2 * p + 1][0] = r[2]; bhf[2 * p + 1][1] = r[3];
        }
#pragma unroll
        for (int mi = 0; mi < 4; mi++)
#pragma unroll
            for (int nj = 0; nj < 4; nj++)
                mma16816(c[mi][nj], ahf[mi], bhf[nj]);
    }

    if (WRITE) {
#pragma unroll
        for (int mi = 0; mi < 4; mi++)
#pragma unroll
            for (int h = 0; h < 2; h++) {
                int rl = wr * 64 + mi * 16 + g + 8 * h;
                float lz = sLz[rl];
                size_t rowbase = (size_t)(row0 + rl) * NN + col0;
#pragma unroll
                for (int nj = 0; nj < 4; nj++) {
                    int cl = wc * 32 + nj * 8 + 2 * t4;
                    float2 o;
                    o.x = c[mi][nj][2 * h]     + sB2[cl]     - lz;
                    o.y = c[mi][nj][2 * h + 1] + sB2[cl + 1] - lz;
                    *(float2*)&C[rowbase + cl] = o;
                }
            }
    } else {
#pragma unroll
        for (int mi = 0; mi < 4; mi++)
#pragma unroll
            for (int h = 0; h < 2; h++) {
                int rl = wr * 64 + mi * 16 + g + 8 * h;
                float v[8];
                float m = -1e30f;
#pragma unroll
                for (int nj = 0; nj < 4; nj++) {
                    int cl = wc * 32 + nj * 8 + 2 * t4;
                    v[2 * nj]     = c[mi][nj][2 * h]     + sB2[cl];
                    v[2 * nj + 1] = c[mi][nj][2 * h + 1] + sB2[cl + 1];
                    m = fmaxf(m, fmaxf(v[2 * nj], v[2 * nj + 1]));
                }
                m = fmaxf(m, __shfl_xor_sync(0xffffffffu, m, 1));
                m = fmaxf(m, __shfl_xor_sync(0xffffffffu, m, 2));
                float s = 0.f;
#pragma unroll
                for (int q = 0; q < 8; q++) s += __expf(v[q] - m);
                s += __shfl_xor_sync(0xffffffffu, s, 1);
                s += __shfl_xor_sync(0xffffffffu, s, 2);
                if (t4 == 0) { sMax[rl * 4 + wc] = m; sSum[rl * 4 + wc] = s; }
            }
        __syncthreads();
        if (tid < 128) {
            float m = -1e30f;
#pragma unroll
            for (int w = 0; w < 4; w++) m = fmaxf(m, sMax[tid * 4 + w]);
            float s = 0.f;
#pragma unroll
            for (int w = 0; w < 4; w++) s += sSum[tid * 4 + w] * __expf(sMax[tid * 4 + w] - m);
            g_pmax[blockIdx.x * NN + row0 + tid] = m;
            g_psum[blockIdx.x * NN + row0 + tid] = s;
        }
    }
}

// ---------------- kernel 7: merge per-colblock stats into lz[row] ----------------
__global__ void k_reduce_lz() {
    int row = blockIdx.x * blockDim.x + threadIdx.x;
    if (row >= NN) return;
    float m = -1e30f;
#pragma unroll 8
    for (int cb = 0; cb < NCB; cb++) m = fmaxf(m, g_pmax[cb * NN + row]);
    float s = 0.f;
#pragma unroll 8
    for (int cb = 0; cb < NCB; cb++)
        s += g_psum[cb * NN + row] * __expf(g_pmax[cb * NN + row] - m);
    g_lz[row] = m + __logf(s);
}

// ---------------- launch ----------------
extern "C" void kernel_launch(void* const* d_in, const int* in_sizes, int n_in,
                              void* d_out, int out_size) {
    const float* x  = (const float*)d_in[0];
    const void*  ei = d_in[1];
    const float* W1 = (const float*)d_in[2];
    const float* b1 = (const float*)d_in[3];
    const float* W2 = (const float*)d_in[4];
    const float* b2 = (const float*)d_in[5];
    float* out = (float*)d_out;

    int E = in_sizes[1] / 2;
    int eblocks = (E + 255) / 256;

    k_init_detect<<<NN / 256, 256>>>((const int*)ei);
    k_hist<<<eblocks, 256>>>(ei, E);
    k_scan<<<1, 1024>>>();
    k_scatter<<<eblocks, 256>>>(ei, E);
    k_xw<<<NN / 64, 256>>>(x, W1);
    k_agg1<<<NN / 8, 256>>>(b1);
    k_agg2<<<NN / 8, 256>>>();
    k_convert<<<(NN * HD / 4) / 256, 256>>>(W2);

    dim3 gg(NCB, NN / 128);
    k_mma<false><<<gg, 256>>>(b2, nullptr);   // stats pass
    k_reduce_lz<<<NN / 256, 256>>>();
    k_mma<true><<<gg, 256>>>(b2, out);        // write pass
}

// round 11
// speedup vs baseline: 1.6624x; 1.0888x over previous
#include <cuda_runtime.h>
#include <cuda_fp16.h>
#include <math.h>
#include <stdint.h>

// Problem constants (fixed shapes for this problem)
#define NN   8192      // nodes (= output classes)
#define FIN  512       // input features
#define HD   64        // hidden dim
#define MAXE (NN * 64) // edges
#define NCB  64        // number of 128-wide column blocks in the big GEMM

// ---------------- device scratch (static allocation; no cudaMalloc) ----------------
__device__ int   g_is64;             // edge_index dtype flag (1 = int64, 0 = int32)
__device__ int   g_hist[NN];         // in-degree histogram (dst counts)
__device__ int   g_row_ptr[NN + 1];  // CSR row pointers (by dst)
__device__ int   g_cursor[NN];       // scatter cursors (preloaded with row starts)
__device__ int   g_col[MAXE];        // CSR column (src) indices
__device__ float g_dinv[NN];         // deg^{-1/2} (deg includes self loop)
__device__ float g_xw[NN * HD];      // x @ W1 (fp32)
__device__ float g_h[NN * HD];       // layer-1 output (post relu, fp32)

// fp16 operands for the tensor-core GEMMs
__device__ __half g_m16[NN * HD];    // M = Â h in fp16, row-major [NN][HD] (written by agg2)
__device__ __half g_w216[HD * NN];   // W2 in fp16, row-major [HD][NN]
__device__ __half g_w116[FIN * HD];  // W1 in fp16, row-major [FIN][HD]

// per-(colblock,row) online softmax stats + final log-normalizer
__device__ float g_pmax[NCB * NN];
__device__ float g_psum[NCB * NN];
__device__ float g_lz[NN];

// ---------------- helpers ----------------
__device__ __forceinline__ int edge_val(const void* ei, long long i) {
    if (g_is64) return (int)((const long long*)ei)[i];
    return ((const int*)ei)[i];
}

__device__ __forceinline__ void ldsm4(uint32_t* r, uint32_t addr) {
    asm volatile("ldmatrix.sync.aligned.m8n8.x4.shared.b16 {%0,%1,%2,%3}, [%4];"
                 : "=r"(r[0]), "=r"(r[1]), "=r"(r[2]), "=r"(r[3]) : "r"(addr));
}
__device__ __forceinline__ void ldsm4t(uint32_t* r, uint32_t addr) {
    asm volatile("ldmatrix.sync.aligned.m8n8.x4.trans.shared.b16 {%0,%1,%2,%3}, [%4];"
                 : "=r"(r[0]), "=r"(r[1]), "=r"(r[2]), "=r"(r[3]) : "r"(addr));
}
__device__ __forceinline__ void mma16816(float* c, const uint32_t* a, const uint32_t* b) {
    asm volatile("mma.sync.aligned.m16n8k16.row.col.f32.f16.f16.f32 "
                 "{%0,%1,%2,%3}, {%4,%5,%6,%7}, {%8,%9}, {%0,%1,%2,%3};"
                 : "+f"(c[0]), "+f"(c[1]), "+f"(c[2]), "+f"(c[3])
                 : "r"(a[0]), "r"(a[1]), "r"(a[2]), "r"(a[3]), "r"(b[0]), "r"(b[1]));
}

// ---------------- kernel W: convert W1, W2 to fp16 (no deps, launched first) ----
__global__ void k_convert_w(const float* __restrict__ W1, const float* __restrict__ W2) {
    int i = blockIdx.x * blockDim.x + threadIdx.x;
    if (i < NN * HD / 4) {
        float4 w4 = *(const float4*)&W2[4 * i];
        __half2* wo = (__half2*)g_w216;
        wo[2 * i]     = __floats2half2_rn(w4.x, w4.y);
        wo[2 * i + 1] = __floats2half2_rn(w4.z, w4.w);
    } else {
        int j = i - NN * HD / 4;   // [0, FIN*HD/4)
        float4 w4 = *(const float4*)&W1[4 * j];
        __half2* wo = (__half2*)g_w116;
        wo[2 * j]     = __floats2half2_rn(w4.x, w4.y);
        wo[2 * j + 1] = __floats2half2_rn(w4.z, w4.w);
    }
}

// ---------------- kernel 0: zero counters + detect int width ----------------
__global__ void k_init_detect(const int* eiw) {
    int t = blockIdx.x * blockDim.x + threadIdx.x;
    if (t < NN) g_hist[t] = 0;
    if (blockIdx.x == 0) {
        __shared__ int cnt;
        if (threadIdx.x == 0) cnt = 0;
        __syncthreads();
        int c = 0;
        for (int i = threadIdx.x; i < 1024; i += blockDim.x)
            if (eiw[2 * i + 1] == 0) c++;
        atomicAdd(&cnt, c);
        __syncthreads();
        if (threadIdx.x == 0) g_is64 = (cnt > 900) ? 1 : 0;
    }
}

// ---------------- kernel 1: histogram of dst ----------------
__global__ void k_hist(const void* ei, int E) {
    int e = blockIdx.x * blockDim.x + threadIdx.x;
    if (e < E) {
        int d = edge_val(ei, (long long)E + e);
        atomicAdd(&g_hist[d], 1);
    }
}

// ---------------- kernel 2: exclusive scan + dinv + cursor preload ----------
__global__ void k_scan() {
    int t = threadIdx.x;
    int vals[8];
    int tsum = 0;
#pragma unroll
    for (int j = 0; j < 8; j++) { vals[j] = g_hist[t * 8 + j]; tsum += vals[j]; }

    int lane = t & 31, wid = t >> 5;
    int incl = tsum;
#pragma unroll
    for (int off = 1; off < 32; off <<= 1) {
        int v = __shfl_up_sync(0xffffffffu, incl, off);
        if (lane >= off) incl += v;
    }
    __shared__ int wsum[32];
    if (lane == 31) wsum[wid] = incl;
    __syncthreads();
    if (wid == 0) {
        int v = wsum[lane];
        int iv = v;
#pragma unroll
        for (int off = 1; off < 32; off <<= 1) {
            int u = __shfl_up_sync(0xffffffffu, iv, off);
            if (lane >= off) iv += u;
        }
        wsum[lane] = iv - v;
    }
    __syncthreads();
    int run = wsum[wid] + (incl - tsum);
#pragma unroll
    for (int j = 0; j < 8; j++) {
        int idx = t * 8 + j;
        g_row_ptr[idx] = run;
        g_cursor[idx]  = run;   // scatter cursor starts at row start
        g_dinv[idx] = rsqrtf((float)vals[j] + 1.0f);
        run += vals[j];
    }
    if (t == 1023) g_row_ptr[NN] = run;
}

// ---------------- kernel 3: scatter src into CSR ----------------
__global__ void k_scatter(const void* ei, int E) {
    int e = blockIdx.x * blockDim.x + threadIdx.x;
    if (e < E) {
        int s = edge_val(ei, e);
        int d = edge_val(ei, (long long)E + e);
        int pos = atomicAdd(&g_cursor[d], 1);
        g_col[pos] = s;
    }
}

// ---------------- kernel 4: XW = x(8192x512) @ W1(512x64) via fp16 MMA ------
// 128-row tile per CTA (grid 64), 8 warps as 4x2 (32 rows x 32 cols each).
// x converted fp32->fp16 while staging tiles; W1 preconverted (g_w116).
__global__ __launch_bounds__(256) void k_xw(const float* __restrict__ x) {
    __shared__ __align__(16) __half Ah[128][72];   // [row][k], 144B stride
    __shared__ __align__(16) __half Bh[64][72];    // [k][col], 144B stride
    int tid = threadIdx.x;
    int row0 = blockIdx.x * 128;
    int lane = tid & 31, wid = tid >> 5;
    int wr = wid >> 1, wc = wid & 1;               // 4x2 warp grid
    int g = lane >> 2, t4 = lane & 3;

    int ra = (lane & 7) + ((lane & 8) ? 8 : 0);
    int ka_off = (lane & 16) ? 8 : 0;
    int rb = (lane & 7) + ((lane & 8) ? 8 : 0);
    int nb_off = (lane & 16) ? 8 : 0;

    float c[2][4][4];
#pragma unroll
    for (int a = 0; a < 2; a++)
#pragma unroll
        for (int b = 0; b < 4; b++)
#pragma unroll
            for (int d = 0; d < 4; d++) c[a][b][d] = 0.f;

    uint32_t ah_base = (uint32_t)__cvta_generic_to_shared(&Ah[0][0]);
    uint32_t bh_base = (uint32_t)__cvta_generic_to_shared(&Bh[0][0]);

    for (int kk0 = 0; kk0 < FIN; kk0 += 64) {
        // x tile: 128 rows x 64 k, fp32 -> fp16
        for (int i = tid; i < 128 * 32; i += 256) {
            int r = i >> 5, c2 = i & 31;
            float2 v = *(const float2*)&x[(size_t)(row0 + r) * FIN + kk0 + 2 * c2];
            *(__half2*)&Ah[r][2 * c2] = __floats2half2_rn(v.x, v.y);
        }
        // W1 tile: 64 k x 64 cols fp16, rows 128B -> 8 uint4
        for (int i = tid; i < 64 * 8; i += 256) {
            int r = i >> 3, q = i & 7;
            *(uint4*)((char*)&Bh[r][0] + q * 16) =
                *(const uint4*)((const char*)(g_w116 + (size_t)(kk0 + r) * HD) + q * 16);
        }
        __syncthreads();
#pragma unroll
        for (int ks = 0; ks < 4; ks++) {
            int k0 = ks * 16;
            uint32_t af[2][4];
#pragma unroll
            for (int mi = 0; mi < 2; mi++) {
                uint32_t off = (uint32_t)((wr * 32 + mi * 16 + ra) * 144 + (k0 + ka_off) * 2);
                ldsm4(af[mi], ah_base + off);
            }
            uint32_t bf[4][2];
#pragma unroll
            for (int p = 0; p < 2; p++) {
                uint32_t off = (uint32_t)((k0 + rb) * 144 + (wc * 32 + p * 16 + nb_off) * 2);
                uint32_t r[4];
                ldsm4t(r, bh_base + off);
                bf[2 * p][0] = r[0]; bf[2 * p][1] = r[1];
                bf[2 * p + 1][0] = r[2]; bf[2 * p + 1][1] = r[3];
            }
#pragma unroll
            for (int mi = 0; mi < 2; mi++)
#pragma unroll
                for (int nj = 0; nj < 4; nj++)
                    mma16816(c[mi][nj], af[mi], bf[nj]);
        }
        __syncthreads();
    }
#pragma unroll
    for (int mi = 0; mi < 2; mi++)
#pragma unroll
        for (int h = 0; h < 2; h++) {
            int rl = wr * 32 + mi * 16 + g + 8 * h;
            size_t base = (size_t)(row0 + rl) * HD;
#pragma unroll
            for (int nj = 0; nj < 4; nj++) {
                int cl = wc * 32 + nj * 8 + 2 * t4;
                *(float2*)&g_xw[base + cl] =
                    make_float2(c[mi][nj][2 * h], c[mi][nj][2 * h + 1]);
            }
        }
}

// ---------------- aggregation core (warp per node, MLP-unrolled) ------------
__device__ __forceinline__ float2 agg_core(const float* __restrict__ in,
                                           int node, int lane, float dn) {
    float2 acc = *(const float2*)&in[(size_t)node * HD + lane * 2];
    acc.x *= dn; acc.y *= dn;   // self loop (pre dinv[dst] factor)

    int beg = g_row_ptr[node], end = g_row_ptr[node + 1];
    int n = end - beg;
    const int* cp = g_col + beg;
    int nfull = n >> 5;
    for (int b = 0; b < nfull; b++, cp += 32) {
        int s = cp[lane];
        float ds = g_dinv[s];
#pragma unroll 8
        for (int j = 0; j < 32; j++) {
            int   ss = __shfl_sync(0xffffffffu, s, j);
            float dd = __shfl_sync(0xffffffffu, ds, j);
            float2 v = *(const float2*)&in[(size_t)ss * HD + lane * 2];
            acc.x += v.x * dd;
            acc.y += v.y * dd;
        }
    }
    int rem = n & 31;
    if (rem) {
        int s = 0; float ds = 0.f;
        if (lane < rem) { s = cp[lane]; ds = g_dinv[s]; }
        for (int j = 0; j < rem; j++) {
            int   ss = __shfl_sync(0xffffffffu, s, j);
            float dd = __shfl_sync(0xffffffffu, ds, j);
            float2 v = *(const float2*)&in[(size_t)ss * HD + lane * 2];
            acc.x += v.x * dd;
            acc.y += v.y * dd;
        }
    }
    return acc;
}

// layer 1: g_h = relu(Â g_xw + b1), fp32 out
__global__ void k_agg1(const float* __restrict__ b1) {
    int gwarp = (blockIdx.x * blockDim.x + threadIdx.x) >> 5;
    int lane = threadIdx.x & 31;
    if (gwarp >= NN) return;
    float dn = g_dinv[gwarp];
    float2 acc = agg_core(g_xw, gwarp, lane, dn);
    float ox = fmaxf(acc.x * dn + b1[lane * 2], 0.f);
    float oy = fmaxf(acc.y * dn + b1[lane * 2 + 1], 0.f);
    *(float2*)&g_h[(size_t)gwarp * HD + lane * 2] = make_float2(ox, oy);
}

// layer 2 aggregation: g_m16 = fp16(Â g_h)  (fused conversion)
__global__ void k_agg2() {
    int gwarp = (blockIdx.x * blockDim.x + threadIdx.x) >> 5;
    int lane = threadIdx.x & 31;
    if (gwarp >= NN) return;
    float dn = g_dinv[gwarp];
    float2 acc = agg_core(g_h, gwarp, lane, dn);
    ((__half2*)g_m16)[(size_t)gwarp * (HD / 2) + lane] =
        __floats2half2_rn(acc.x * dn, acc.y * dn);
}

// ---------------- kernel 6: fp16 MMA GEMM, 128x128 tile, 8 warps ----------------
// WRITE=false: compute logits tile, emit per-(colblock,row) (max, sumexp) only.
// WRITE=true : recompute, write  acc + b2[col] - lz[row]  to C.
template <bool WRITE>
__global__ __launch_bounds__(256) void k_mma(const float* __restrict__ b2,
                                             float* __restrict__ C) {
    __shared__ __align__(16) __half Ah[128][72];   // [row][k], 144B stride
    __shared__ __align__(16) __half Bh[64][136];   // [k][col], 272B stride
    __shared__ float sB2[128];
    __shared__ float sLz[128];

    int tid = threadIdx.x;
    int row0 = blockIdx.y * 128, col0 = blockIdx.x * 128;

    // load A (M rows fp16), rows are 128B -> 8 uint4 each
    for (int i = tid; i < 1024; i += 256) {
        int r = i >> 3, q = i & 7;
        *(uint4*)((char*)&Ah[r][0] + q * 16) =
            *(const uint4*)((const char*)(g_m16 + (size_t)(row0 + r) * HD) + q * 16);
    }
    // load B (W2 tile 64 x 128 fp16), rows are 256B -> 16 uint4 each
    for (int i = tid; i < 1024; i += 256) {
        int r = i >> 4, q = i & 15;
        *(uint4*)((char*)&Bh[r][0] + q * 16) =
            *(const uint4*)((const char*)(g_w216 + (size_t)r * NN + col0) + q * 16);
    }
    if (tid < 128) {
        sB2[tid] = b2[col0 + tid];
        if (WRITE) sLz[tid] = g_lz[row0 + tid];
    }
    __syncthreads();

    int lane = tid & 31, wid = tid >> 5;
    int wr = wid >> 2, wc = wid & 3;      // warp tile: rows [wr*64,+64), cols [wc*32,+32)
    int g = lane >> 2, t4 = lane & 3;

    float c[4][4][4];
#pragma unroll
    for (int a = 0; a < 4; a++)
#pragma unroll
        for (int b = 0; b < 4; b++)
#pragma unroll
            for (int d = 0; d < 4; d++) c[a][b][d] = 0.f;

    uint32_t ah_base = (uint32_t)__cvta_generic_to_shared(&Ah[0][0]);
    uint32_t bh_base = (uint32_t)__cvta_generic_to_shared(&Bh[0][0]);

    int ra = (lane & 7) + ((lane & 8) ? 8 : 0);
    int ka_off = (lane & 16) ? 8 : 0;
    int rb = (lane & 7) + ((lane & 8) ? 8 : 0);
    int nb_off = (lane & 16) ? 8 : 0;

#pragma unroll
    for (int ks = 0; ks < 4; ks++) {
        int k0 = ks * 16;
        uint32_t ahf[4][4];
#pragma unroll
        for (int mi = 0; mi < 4; mi++) {
            uint32_t off = (uint32_t)((wr * 64 + mi * 16 + ra) * 144 + (k0 + ka_off) * 2);
            ldsm4(ahf[mi], ah_base + off);
        }
        uint32_t bhf[4][2];
#pragma unroll
        for (int p = 0; p < 2; p++) {
            uint32_t off = (uint32_t)((k0 + rb) * 272 + (wc * 32 + p * 16 + nb_off) * 2);
            uint32_t r[4];
            ldsm4t(r, bh_base + off);
            bhf[2 * p][0] = r[0]; bhf[2 * p][1] = r[1];
            bhf[2 * p + 1][0] = r[2]; bhf[2 * p + 1][1] = r[3];
        }
#pragma unroll
        for (int mi = 0; mi < 4; mi++)
#pragma unroll
            for (int nj = 0; nj < 4; nj++)
                mma16816(c[mi][nj], ahf[mi], bhf[nj]);
    }

    if (WRITE) {
#pragma unroll
        for (int mi = 0; mi < 4; mi++)
#pragma unroll
            for (int h = 0; h < 2; h++) {
                int rl = wr * 64 + mi * 16 + g + 8 * h;
                float lz = sLz[rl];
                size_t rowbase = (size_t)(row0 + rl) * NN + col0;
#pragma unroll
                for (int nj = 0; nj < 4; nj++) {
                    int cl = wc * 32 + nj * 8 + 2 * t4;
                    float2 o;
                    o.x = c[mi][nj][2 * h]     + sB2[cl]     - lz;
                    o.y = c[mi][nj][2 * h + 1] + sB2[cl + 1] - lz;
                    *(float2*)&C[rowbase + cl] = o;
                }
            }
    } else {
        __syncthreads();                   // done with Ah; overlay stats arrays
        float* sMax = (float*)&Ah[0][0];   // 512 floats
        float* sSum = sMax + 512;
#pragma unroll
        for (int mi = 0; mi < 4; mi++)
#pragma unroll
            for (int h = 0; h < 2; h++) {
                int rl = wr * 64 + mi * 16 + g + 8 * h;
                float v[8];
                float m = -1e30f;
#pragma unroll
                for (int nj = 0; nj < 4; nj++) {
                    int cl = wc * 32 + nj * 8 + 2 * t4;
                    v[2 * nj]     = c[mi][nj][2 * h]     + sB2[cl];
                    v[2 * nj + 1] = c[mi][nj][2 * h + 1] + sB2[cl + 1];
                    m = fmaxf(m, fmaxf(v[2 * nj], v[2 * nj + 1]));
                }
                m = fmaxf(m, __shfl_xor_sync(0xffffffffu, m, 1));
                m = fmaxf(m, __shfl_xor_sync(0xffffffffu, m, 2));
                float s = 0.f;
#pragma unroll
                for (int q = 0; q < 8; q++) s += __expf(v[q] - m);
                s += __shfl_xor_sync(0xffffffffu, s, 1);
                s += __shfl_xor_sync(0xffffffffu, s, 2);
                if (t4 == 0) { sMax[rl * 4 + wc] = m; sSum[rl * 4 + wc] = s; }
            }
        __syncthreads();
        if (tid < 128) {
            float m = -1e30f;
#pragma unroll
            for (int w = 0; w < 4; w++) m = fmaxf(m, sMax[tid * 4 + w]);
            float s = 0.f;
#pragma unroll
            for (int w = 0; w < 4; w++) s += sSum[tid * 4 + w] * __expf(sMax[tid * 4 + w] - m);
            g_pmax[blockIdx.x * NN + row0 + tid] = m;
            g_psum[blockIdx.x * NN + row0 + tid] = s;
        }
    }
}

// ---------------- kernel 7: merge per-colblock stats into lz[row] ----------------
__global__ void k_reduce_lz() {
    int row = blockIdx.x * blockDim.x + threadIdx.x;
    if (row >= NN) return;
    float m = -1e30f;
#pragma unroll 8
    for (int cb = 0; cb < NCB; cb++) m = fmaxf(m, g_pmax[cb * NN + row]);
    float s = 0.f;
#pragma unroll 8
    for (int cb = 0; cb < NCB; cb++)
        s += g_psum[cb * NN + row] * __expf(g_pmax[cb * NN + row] - m);
    g_lz[row] = m + __logf(s);
}

// ---------------- launch ----------------
extern "C" void kernel_launch(void* const* d_in, const int* in_sizes, int n_in,
                              void* d_out, int out_size) {
    const float* x  = (const float*)d_in[0];
    const void*  ei = d_in[1];
    const float* W1 = (const float*)d_in[2];
    const float* b1 = (const float*)d_in[3];
    const float* W2 = (const float*)d_in[4];
    const float* b2 = (const float*)d_in[5];
    float* out = (float*)d_out;

    int E = in_sizes[1] / 2;
    int eblocks = (E + 255) / 256;

    k_convert_w<<<(NN * HD / 4 + FIN * HD / 4) / 256, 256>>>(W1, W2);
    k_init_detect<<<NN / 256, 256>>>((const int*)ei);
    k_hist<<<eblocks, 256>>>(ei, E);
    k_scan<<<1, 1024>>>();
    k_scatter<<<eblocks, 256>>>(ei, E);
    k_xw<<<NN / 128, 256>>>(x);
    k_agg1<<<NN / 8, 256>>>(b1);
    k_agg2<<<NN / 8, 256>>>();

    dim3 gg(NCB, NN / 128);
    k_mma<false><<<gg, 256>>>(b2, nullptr);   // stats pass
    k_reduce_lz<<<NN / 256, 256>>>();
    k_mma<true><<<gg, 256>>>(b2, out);        // write pass
}

// round 12
// speedup vs baseline: 1.9723x; 1.1864x over previous
#include <cuda_runtime.h>
#include <cuda_fp16.h>
#include <math.h>
#include <stdint.h>

// Problem constants (fixed shapes for this problem)
#define NN   8192      // nodes (= output classes)
#define FIN  512       // input features
#define HD   64        // hidden dim
#define MAXE (NN * 64) // edges
#define NCB  64        // number of 128-wide column blocks in the big GEMM

// ---------------- device scratch (static allocation; no cudaMalloc) ----------------
__device__ int   g_is64;             // edge_index dtype flag (1 = int64, 0 = int32)
__device__ int   g_hist[NN];         // in-degree histogram (dst counts)
__device__ int   g_bsum[32];         // scan: per-block sums
__device__ int   g_boff[32];         // scan: per-block exclusive offsets
__device__ int   g_row_ptr[NN + 1];  // CSR row pointers (by dst)
__device__ int   g_cursor[NN];       // scatter cursors (preloaded with row starts)
__device__ int   g_col[MAXE];        // CSR column (src) indices
__device__ float g_dinv[NN];         // deg^{-1/2} (deg includes self loop)

// fp16 feature arrays (half the gather traffic in the aggregations)
__device__ __half g_xw16[NN * HD];   // x @ W1, fp16 [NN][HD]
__device__ __half g_h16[NN * HD];    // layer-1 output (post relu), fp16
__device__ __half g_m16[NN * HD];    // M = Â h in fp16 (written by agg2)
__device__ __half g_w216[HD * NN];   // W2 in fp16, row-major [HD][NN]
__device__ __half g_w116[FIN * HD];  // W1 in fp16, row-major [FIN][HD]

// per-(colblock,row) online softmax stats + final log-normalizer
__device__ float g_pmax[NCB * NN];
__device__ float g_psum[NCB * NN];
__device__ float g_lz[NN];

// ---------------- helpers ----------------
__device__ __forceinline__ void ldsm4(uint32_t* r, uint32_t addr) {
    asm volatile("ldmatrix.sync.aligned.m8n8.x4.shared.b16 {%0,%1,%2,%3}, [%4];"
                 : "=r"(r[0]), "=r"(r[1]), "=r"(r[2]), "=r"(r[3]) : "r"(addr));
}
__device__ __forceinline__ void ldsm4t(uint32_t* r, uint32_t addr) {
    asm volatile("ldmatrix.sync.aligned.m8n8.x4.trans.shared.b16 {%0,%1,%2,%3}, [%4];"
                 : "=r"(r[0]), "=r"(r[1]), "=r"(r[2]), "=r"(r[3]) : "r"(addr));
}
__device__ __forceinline__ void mma16816(float* c, const uint32_t* a, const uint32_t* b) {
    asm volatile("mma.sync.aligned.m16n8k16.row.col.f32.f16.f16.f32 "
                 "{%0,%1,%2,%3}, {%4,%5,%6,%7}, {%8,%9}, {%0,%1,%2,%3};"
                 : "+f"(c[0]), "+f"(c[1]), "+f"(c[2]), "+f"(c[3])
                 : "r"(a[0]), "r"(a[1]), "r"(a[2]), "r"(a[3]), "r"(b[0]), "r"(b[1]));
}

// ---------------- kernel W: convert W1, W2 to fp16 + zero hist (no deps) ----
__global__ void k_convert_w(const float* __restrict__ W1, const float* __restrict__ W2) {
    int i = blockIdx.x * blockDim.x + threadIdx.x;
    if (i < NN) g_hist[i] = 0;
    if (i < NN * HD / 4) {
        float4 w4 = *(const float4*)&W2[4 * i];
        __half2* wo = (__half2*)g_w216;
        wo[2 * i]     = __floats2half2_rn(w4.x, w4.y);
        wo[2 * i + 1] = __floats2half2_rn(w4.z, w4.w);
    } else {
        int j = i - NN * HD / 4;   // [0, FIN*HD/4)
        float4 w4 = *(const float4*)&W1[4 * j];
        __half2* wo = (__half2*)g_w116;
        wo[2 * j]     = __floats2half2_rn(w4.x, w4.y);
        wo[2 * j + 1] = __floats2half2_rn(w4.z, w4.w);
    }
}

// ---------------- kernel 1: histogram of dst (per-block int-width detect) ----
__global__ void k_hist(const void* ei, const int* eiw, int E) {
    __shared__ int s_cnt;
    int t = threadIdx.x;
    if (t == 0) s_cnt = 0;
    __syncthreads();
    if (t < 256) {
        // inspect odd 32-bit words: all ~0 => int64 (ids < 8192), random => int32
        unsigned zero = __ballot_sync(0xffffffffu, eiw[2 * t + 1] == 0);
        if ((t & 31) == 0) atomicAdd(&s_cnt, __popc(zero));
    }
    __syncthreads();
    int is64 = s_cnt > 200;
    if (blockIdx.x == 0 && t == 0) g_is64 = is64;   // for k_scatter
    int e = blockIdx.x * blockDim.x + t;
    if (e < E) {
        int d = is64 ? (int)((const long long*)ei)[(long long)E + e]
                     : ((const int*)ei)[E + e];
        atomicAdd(&g_hist[d], 1);
    }
}

// ---------------- scan (3 small kernels, multi-block) -----------------------
// A: per-block (256-wide) sums
__global__ void k_scan_a() {
    int t = threadIdx.x, lane = t & 31, wid = t >> 5;
    int v = g_hist[blockIdx.x * 256 + t];
    int s = v;
#pragma unroll
    for (int off = 16; off > 0; off >>= 1) s += __shfl_xor_sync(0xffffffffu, s, off);
    __shared__ int ws[8];
    if (lane == 0) ws[wid] = s;
    __syncthreads();
    if (t == 0) {
        int tot = 0;
#pragma unroll
        for (int w = 0; w < 8; w++) tot += ws[w];
        g_bsum[blockIdx.x] = tot;
    }
}
// B: spine scan of 32 block sums (1 warp)
__global__ void k_scan_b() {
    int lane = threadIdx.x;
    int v = g_bsum[lane];
    int incl = v;
#pragma unroll
    for (int off = 1; off < 32; off <<= 1) {
        int u = __shfl_up_sync(0xffffffffu, incl, off);
        if (lane >= off) incl += u;
    }
    g_boff[lane] = incl - v;
    if (lane == 31) g_row_ptr[NN] = incl;
}
// C: final prefix + write row_ptr / cursor / dinv
__global__ void k_scan_c() {
    int t = threadIdx.x, lane = t & 31, wid = t >> 5;
    int idx = blockIdx.x * 256 + t;
    int v = g_hist[idx];
    int incl = v;
#pragma unroll
    for (int off = 1; off < 32; off <<= 1) {
        int u = __shfl_up_sync(0xffffffffu, incl, off);
        if (lane >= off) incl += u;
    }
    __shared__ int ws[8];
    if (lane == 31) ws[wid] = incl;
    __syncthreads();
    if (wid == 0 && lane < 8) {
        int wv = ws[lane];
        int wi = wv;
#pragma unroll
        for (int off = 1; off < 8; off <<= 1) {
            int u = __shfl_up_sync(0xffu, wi, off);
            if (lane >= off) wi += u;
        }
        ws[lane] = wi - wv;
    }
    __syncthreads();
    int excl = g_boff[blockIdx.x] + ws[wid] + incl - v;
    g_row_ptr[idx] = excl;
    g_cursor[idx]  = excl;
    g_dinv[idx] = rsqrtf((float)v + 1.0f);
}

// ---------------- kernel 3: scatter src into CSR ----------------------------
__global__ void k_scatter(const void* ei, int E) {
    int e = blockIdx.x * blockDim.x + threadIdx.x;
    if (e < E) {
        int s, d;
        if (g_is64) {
            s = (int)((const long long*)ei)[e];
            d = (int)((const long long*)ei)[(long long)E + e];
        } else {
            s = ((const int*)ei)[e];
            d = ((const int*)ei)[E + e];
        }
        int pos = atomicAdd(&g_cursor[d], 1);
        g_col[pos] = s;
    }
}

// ---------------- kernel 4: XW = x(8192x512) @ W1(512x64) via fp16 MMA ------
// 128-row tile per CTA (grid 64), 8 warps as 4x2 (32 rows x 32 cols each).
__global__ __launch_bounds__(256) void k_xw(const float* __restrict__ x) {
    __shared__ __align__(16) __half Ah[128][72];   // [row][k], 144B stride
    __shared__ __align__(16) __half Bh[64][72];    // [k][col], 144B stride
    int tid = threadIdx.x;
    int row0 = blockIdx.x * 128;
    int lane = tid & 31, wid = tid >> 5;
    int wr = wid >> 1, wc = wid & 1;               // 4x2 warp grid
    int g = lane >> 2, t4 = lane & 3;

    int ra = (lane & 7) + ((lane & 8) ? 8 : 0);
    int ka_off = (lane & 16) ? 8 : 0;
    int rb = (lane & 7) + ((lane & 8) ? 8 : 0);
    int nb_off = (lane & 16) ? 8 : 0;

    float c[2][4][4];
#pragma unroll
    for (int a = 0; a < 2; a++)
#pragma unroll
        for (int b = 0; b < 4; b++)
#pragma unroll
            for (int d = 0; d < 4; d++) c[a][b][d] = 0.f;

    uint32_t ah_base = (uint32_t)__cvta_generic_to_shared(&Ah[0][0]);
    uint32_t bh_base = (uint32_t)__cvta_generic_to_shared(&Bh[0][0]);

    for (int kk0 = 0; kk0 < FIN; kk0 += 64) {
        for (int i = tid; i < 128 * 32; i += 256) {
            int r = i >> 5, c2 = i & 31;
            float2 v = *(const float2*)&x[(size_t)(row0 + r) * FIN + kk0 + 2 * c2];
            *(__half2*)&Ah[r][2 * c2] = __floats2half2_rn(v.x, v.y);
        }
        for (int i = tid; i < 64 * 8; i += 256) {
            int r = i >> 3, q = i & 7;
            *(uint4*)((char*)&Bh[r][0] + q * 16) =
                *(const uint4*)((const char*)(g_w116 + (size_t)(kk0 + r) * HD) + q * 16);
        }
        __syncthreads();
#pragma unroll
        for (int ks = 0; ks < 4; ks++) {
            int k0 = ks * 16;
            uint32_t af[2][4];
#pragma unroll
            for (int mi = 0; mi < 2; mi++) {
                uint32_t off = (uint32_t)((wr * 32 + mi * 16 + ra) * 144 + (k0 + ka_off) * 2);
                ldsm4(af[mi], ah_base + off);
            }
            uint32_t bf[4][2];
#pragma unroll
            for (int p = 0; p < 2; p++) {
                uint32_t off = (uint32_t)((k0 + rb) * 144 + (wc * 32 + p * 16 + nb_off) * 2);
                uint32_t r[4];
                ldsm4t(r, bh_base + off);
                bf[2 * p][0] = r[0]; bf[2 * p][1] = r[1];
                bf[2 * p + 1][0] = r[2]; bf[2 * p + 1][1] = r[3];
            }
#pragma unroll
            for (int mi = 0; mi < 2; mi++)
#pragma unroll
                for (int nj = 0; nj < 4; nj++)
                    mma16816(c[mi][nj], af[mi], bf[nj]);
        }
        __syncthreads();
    }
#pragma unroll
    for (int mi = 0; mi < 2; mi++)
#pragma unroll
        for (int h = 0; h < 2; h++) {
            int rl = wr * 32 + mi * 16 + g + 8 * h;
            size_t base = (size_t)(row0 + rl) * HD;
#pragma unroll
            for (int nj = 0; nj < 4; nj++) {
                int cl = wc * 32 + nj * 8 + 2 * t4;
                *(__half2*)&g_xw16[base + cl] =
                    __floats2half2_rn(c[mi][nj][2 * h], c[mi][nj][2 * h + 1]);
            }
        }
}

// ---------------- aggregation core (warp per node, fp16 gathers) ------------
__device__ __forceinline__ float2 agg_core(const __half* __restrict__ in,
                                           int node, int lane, float dn) {
    const __half2* in2 = (const __half2*)in;
    float2 acc = __half22float2(in2[(size_t)node * 32 + lane]);
    acc.x *= dn; acc.y *= dn;   // self loop (pre dinv[dst] factor)

    int beg = g_row_ptr[node], end = g_row_ptr[node + 1];
    int n = end - beg;
    const int* cp = g_col + beg;
    int nfull = n >> 5;
    for (int b = 0; b < nfull; b++, cp += 32) {
        int s = cp[lane];
        float ds = g_dinv[s];
#pragma unroll 8
        for (int j = 0; j < 32; j++) {
            int   ss = __shfl_sync(0xffffffffu, s, j);
            float dd = __shfl_sync(0xffffffffu, ds, j);
            float2 v = __half22float2(in2[(size_t)ss * 32 + lane]);
            acc.x += v.x * dd;
            acc.y += v.y * dd;
        }
    }
    int rem = n & 31;
    if (rem) {
        int s = 0; float ds = 0.f;
        if (lane < rem) { s = cp[lane]; ds = g_dinv[s]; }
        for (int j = 0; j < rem; j++) {
            int   ss = __shfl_sync(0xffffffffu, s, j);
            float dd = __shfl_sync(0xffffffffu, ds, j);
            float2 v = __half22float2(in2[(size_t)ss * 32 + lane]);
            acc.x += v.x * dd;
            acc.y += v.y * dd;
        }
    }
    return acc;
}

// layer 1: g_h16 = fp16(relu(Â g_xw16 + b1))
__global__ void k_agg1(const float* __restrict__ b1) {
    int gwarp = (blockIdx.x * blockDim.x + threadIdx.x) >> 5;
    int lane = threadIdx.x & 31;
    if (gwarp >= NN) return;
    float dn = g_dinv[gwarp];
    float2 acc = agg_core(g_xw16, gwarp, lane, dn);
    float ox = fmaxf(acc.x * dn + b1[lane * 2], 0.f);
    float oy = fmaxf(acc.y * dn + b1[lane * 2 + 1], 0.f);
    ((__half2*)g_h16)[(size_t)gwarp * 32 + lane] = __floats2half2_rn(ox, oy);
}

// layer 2 aggregation: g_m16 = fp16(Â g_h16)
__global__ void k_agg2() {
    int gwarp = (blockIdx.x * blockDim.x + threadIdx.x) >> 5;
    int lane = threadIdx.x & 31;
    if (gwarp >= NN) return;
    float dn = g_dinv[gwarp];
    float2 acc = agg_core(g_h16, gwarp, lane, dn);
    ((__half2*)g_m16)[(size_t)gwarp * 32 + lane] =
        __floats2half2_rn(acc.x * dn, acc.y * dn);
}

// ---------------- kernel 6: fp16 MMA GEMM, 128x128 tile, 8 warps ----------------
// WRITE=false: compute logits tile, emit per-(colblock,row) (max, sumexp) only.
// WRITE=true : recompute, write  acc + b2[col] - lz[row]  to C (streaming stores).
template <bool WRITE>
__global__ __launch_bounds__(256) void k_mma(const float* __restrict__ b2,
                                             float* __restrict__ C) {
    __shared__ __align__(16) __half Ah[128][72];   // [row][k], 144B stride
    __shared__ __align__(16) __half Bh[64][136];   // [k][col], 272B stride
    __shared__ float sB2[128];
    __shared__ float sLz[128];

    int tid = threadIdx.x;
    int row0 = blockIdx.y * 128, col0 = blockIdx.x * 128;

    for (int i = tid; i < 1024; i += 256) {
        int r = i >> 3, q = i & 7;
        *(uint4*)((char*)&Ah[r][0] + q * 16) =
            *(const uint4*)((const char*)(g_m16 + (size_t)(row0 + r) * HD) + q * 16);
    }
    for (int i = tid; i < 1024; i += 256) {
        int r = i >> 4, q = i & 15;
        *(uint4*)((char*)&Bh[r][0] + q * 16) =
            *(const uint4*)((const char*)(g_w216 + (size_t)r * NN + col0) + q * 16);
    }
    if (tid < 128) {
        sB2[tid] = b2[col0 + tid];
        if (WRITE) sLz[tid] = g_lz[row0 + tid];
    }
    __syncthreads();

    int lane = tid & 31, wid = tid >> 5;
    int wr = wid >> 2, wc = wid & 3;      // warp tile: rows [wr*64,+64), cols [wc*32,+32)
    int g = lane >> 2, t4 = lane & 3;

    float c[4][4][4];
#pragma unroll
    for (int a = 0; a < 4; a++)
#pragma unroll
        for (int b = 0; b < 4; b++)
#pragma unroll
            for (int d = 0; d < 4; d++) c[a][b][d] = 0.f;

    uint32_t ah_base = (uint32_t)__cvta_generic_to_shared(&Ah[0][0]);
    uint32_t bh_base = (uint32_t)__cvta_generic_to_shared(&Bh[0][0]);

    int ra = (lane & 7) + ((lane & 8) ? 8 : 0);
    int ka_off = (lane & 16) ? 8 : 0;
    int rb = (lane & 7) + ((lane & 8) ? 8 : 0);
    int nb_off = (lane & 16) ? 8 : 0;

#pragma unroll
    for (int ks = 0; ks < 4; ks++) {
        int k0 = ks * 16;
        uint32_t ahf[4][4];
#pragma unroll
        for (int mi = 0; mi < 4; mi++) {
            uint32_t off = (uint32_t)((wr * 64 + mi * 16 + ra) * 144 + (k0 + ka_off) * 2);
            ldsm4(ahf[mi], ah_base + off);
        }
        uint32_t bhf[4][2];
#pragma unroll
        for (int p = 0; p < 2; p++) {
            uint32_t off = (uint32_t)((k0 + rb) * 272 + (wc * 32 + p * 16 + nb_off) * 2);
            uint32_t r[4];
            ldsm4t(r, bh_base + off);
            bhf[2 * p][0] = r[0]; bhf[2 * p][1] = r[1];
            bhf[2 * p + 1][0] = r[2]; bhf[2 * p + 1][1] = r[3];
        }
#pragma unroll
        for (int mi = 0; mi < 4; mi++)
#pragma unroll
            for (int nj = 0; nj < 4; nj++)
                mma16816(c[mi][nj], ahf[mi], bhf[nj]);
    }

    if (WRITE) {
#pragma unroll
        for (int mi = 0; mi < 4; mi++)
#pragma unroll
            for (int h = 0; h < 2; h++) {
                int rl = wr * 64 + mi * 16 + g + 8 * h;
                float lz = sLz[rl];
                size_t rowbase = (size_t)(row0 + rl) * NN + col0;
#pragma unroll
                for (int nj = 0; nj < 4; nj++) {
                    int cl = wc * 32 + nj * 8 + 2 * t4;
                    float2 o;
                    o.x = c[mi][nj][2 * h]     + sB2[cl]     - lz;
                    o.y = c[mi][nj][2 * h + 1] + sB2[cl + 1] - lz;
                    __stcs((float2*)&C[rowbase + cl], o);
                }
            }
    } else {
        __syncthreads();                   // done with Ah; overlay stats arrays
        float* sMax = (float*)&Ah[0][0];   // 512 floats
        float* sSum = sMax + 512;
#pragma unroll
        for (int mi = 0; mi < 4; mi++)
#pragma unroll
            for (int h = 0; h < 2; h++) {
                int rl = wr * 64 + mi * 16 + g + 8 * h;
                float v[8];
                float m = -1e30f;
#pragma unroll
                for (int nj = 0; nj < 4; nj++) {
                    int cl = wc * 32 + nj * 8 + 2 * t4;
                    v[2 * nj]     = c[mi][nj][2 * h]     + sB2[cl];
                    v[2 * nj + 1] = c[mi][nj][2 * h + 1] + sB2[cl + 1];
                    m = fmaxf(m, fmaxf(v[2 * nj], v[2 * nj + 1]));
                }
                m = fmaxf(m, __shfl_xor_sync(0xffffffffu, m, 1));
                m = fmaxf(m, __shfl_xor_sync(0xffffffffu, m, 2));
                float s = 0.f;
#pragma unroll
                for (int q = 0; q < 8; q++) s += __expf(v[q] - m);
                s += __shfl_xor_sync(0xffffffffu, s, 1);
                s += __shfl_xor_sync(0xffffffffu, s, 2);
                if (t4 == 0) { sMax[rl * 4 + wc] = m; sSum[rl * 4 + wc] = s; }
            }
        __syncthreads();
        if (tid < 128) {
            float m = -1e30f;
#pragma unroll
            for (int w = 0; w < 4; w++) m = fmaxf(m, sMax[tid * 4 + w]);
            float s = 0.f;
#pragma unroll
            for (int w = 0; w < 4; w++) s += sSum[tid * 4 + w] * __expf(sMax[tid * 4 + w] - m);
            g_pmax[blockIdx.x * NN + row0 + tid] = m;
            g_psum[blockIdx.x * NN + row0 + tid] = s;
        }
    }
}

// ---------------- kernel 7: merge per-colblock stats into lz[row] ----------------
__global__ void k_reduce_lz() {
    int row = blockIdx.x * blockDim.x + threadIdx.x;
    if (row >= NN) return;
    float m = -1e30f;
#pragma unroll 8
    for (int cb = 0; cb < NCB; cb++) m = fmaxf(m, g_pmax[cb * NN + row]);
    float s = 0.f;
#pragma unroll 8
    for (int cb = 0; cb < NCB; cb++)
        s += g_psum[cb * NN + row] * __expf(g_pmax[cb * NN + row] - m);
    g_lz[row] = m + __logf(s);
}

// ---------------- launch ----------------
extern "C" void kernel_launch(void* const* d_in, const int* in_sizes, int n_in,
                              void* d_out, int out_size) {
    const float* x  = (const float*)d_in[0];
    const void*  ei = d_in[1];
    const float* W1 = (const float*)d_in[2];
    const float* b1 = (const float*)d_in[3];
    const float* W2 = (const float*)d_in[4];
    const float* b2 = (const float*)d_in[5];
    float* out = (float*)d_out;

    int E = in_sizes[1] / 2;
    int eblocks = (E + 255) / 256;

    k_convert_w<<<(NN * HD / 4 + FIN * HD / 4 + 255) / 256, 256>>>(W1, W2);
    k_hist<<<eblocks, 256>>>(ei, (const int*)ei, E);
    k_scan_a<<<32, 256>>>();
    k_scan_b<<<1, 32>>>();
    k_scan_c<<<32, 256>>>();
    k_scatter<<<eblocks, 256>>>(ei, E);
    k_xw<<<NN / 128, 256>>>(x);
    k_agg1<<<NN / 8, 256>>>(b1);
    k_agg2<<<NN / 8, 256>>>();

    dim3 gg(NCB, NN / 128);
    k_mma<false><<<gg, 256>>>(b2, nullptr);   // stats pass
    k_reduce_lz<<<NN / 256, 256>>>();
    k_mma<true><<<gg, 256>>>(b2, out);        // write pass
}